// round 1
// baseline (speedup 1.0000x reference)
#include <cuda_runtime.h>
#include <cstdint>

#define BB  32
#define CC  128
#define HH  56
#define WWd 56
#define HWP 3136
#define EE  4
#define THETA 0.7f
#define BN_EPS 1e-5f

// ---------------- scratch (device globals; no allocation allowed) ----------
__device__ float g_pool[BB*CC];
__device__ int   g_sel[BB];
__device__ float g_weff[CC*CC*9];          // CD effective 3x3 weights
__device__ float g_k5[CC*CC*25];           // Bayar 5x5 kernel
__device__ float g_y2[(size_t)BB*3*CC*HWP]; // SRM depthwise out (clipped)
__device__ float g_z2[(size_t)BB*CC*HWP];   // SRM 1x1 out (pre-BN)
__device__ float g_y3[(size_t)BB*CC*HWP];   // HF depthwise out
__device__ float g_z3[(size_t)BB*CC*HWP];   // HF 1x1 out (pre-BN)
__device__ float g_sum2[CC], g_sq2[CC], g_sum3[CC], g_sq3[CC];
__device__ float g_mrs2[2*CC], g_mrs3[2*CC]; // mean, rsqrt(var+eps)

// ---------------- gating ---------------------------------------------------
__global__ void pool_kernel(const float* __restrict__ x) {
    int bc = blockIdx.x;
    const float* p = x + (size_t)bc * HWP;
    float s = 0.f;
    for (int i = threadIdx.x; i < HWP; i += 256) s += p[i];
    __shared__ float sm[256];
    sm[threadIdx.x] = s; __syncthreads();
    for (int o = 128; o > 0; o >>= 1) {
        if (threadIdx.x < o) sm[threadIdx.x] += sm[threadIdx.x + o];
        __syncthreads();
    }
    if (threadIdx.x == 0) g_pool[bc] = sm[0] * (1.0f / (float)HWP);
}

__global__ void gating_kernel(const float* __restrict__ Wg, float* __restrict__ tail) {
    int b = threadIdx.x;
    __shared__ float cnt[EE];
    if (b < EE) cnt[b] = 0.f;
    __syncthreads();
    if (b < BB) {
        float logit[EE];
        for (int e = 0; e < EE; e++) {
            float s = 0.f;
            for (int c = 0; c < CC; c++) s += g_pool[b*CC + c] * Wg[c*EE + e];
            logit[e] = s;
        }
        int best = 0; float bv = logit[0];
        for (int e = 1; e < EE; e++) if (logit[e] > bv) { bv = logit[e]; best = e; }
        g_sel[b] = best;
        for (int e = 0; e < EE; e++) tail[9 + b*EE + e] = (e == best) ? 1.0f : 0.0f;
        atomicAdd(&cnt[best], 1.0f);
    }
    __syncthreads();
    if (b == 0) {
        float mean = 0.f;
        for (int e = 0; e < EE; e++) mean += cnt[e];
        mean *= (1.0f / EE);
        float var = 0.f;
        for (int e = 0; e < EE; e++) { float d = cnt[e] - mean; var += d*d; }
        var *= (1.0f / EE);
        tail[0] = var / (mean*mean + 1e-10f);          // aux_loss
        for (int e = 0; e < EE; e++) {
            tail[1 + e] = cnt[e];                       // examples_per_expert
            tail[5 + e] = cnt[e];                       // expert_importance
        }
    }
}

// ---------------- weight prep ----------------------------------------------
__global__ void prep_cd(const float* __restrict__ cd_w) {
    int oi = blockIdx.x * blockDim.x + threadIdx.x;
    if (oi >= CC*CC) return;
    const float* w = cd_w + (size_t)oi * 9;
    float s = 0.f;
    #pragma unroll
    for (int t = 0; t < 9; t++) s += w[t];
    #pragma unroll
    for (int t = 0; t < 9; t++)
        g_weff[(size_t)oi*9 + t] = w[t] - ((t == 4) ? THETA * s : 0.f);
}

__global__ void prep_bayar(const float* __restrict__ raw) {
    int oi = blockIdx.x * blockDim.x + threadIdx.x;
    if (oi >= CC*CC) return;
    const float* r = raw + (size_t)oi * 24;
    float s = 0.f;
    #pragma unroll
    for (int t = 0; t < 24; t++) s += r[t];
    float inv = 1.0f / s;
    float* k = g_k5 + (size_t)oi * 25;
    #pragma unroll
    for (int t = 0; t < 12; t++) k[t] = r[t] * inv;
    k[12] = -1.0f;
    #pragma unroll
    for (int t = 12; t < 24; t++) k[t+1] = r[t] * inv;
}

// ---------------- direct 3x3 conv (dense or gated) --------------------------
// block: 32 out-channels x 8x8 pixels, 128 threads, each thread 4co x 4px
template<int SEL, bool ACCUM>
__global__ __launch_bounds__(128) void conv3_kernel(
    const float* __restrict__ x, const float* __restrict__ w, float* __restrict__ out)
{
    int b = blockIdx.z;
    if (SEL >= 0 && g_sel[b] != SEL) return;
    int tile = blockIdx.x;             // 49 tiles
    int ty = tile / 7, tx = tile % 7;
    int coBase = blockIdx.y * 32;

    __shared__ float sIn[8][10][10];
    __shared__ float sW[8][9][32];

    int tid = threadIdx.x;
    int quad = tid & 15, grp = tid >> 4;
    int pr = quad >> 1, pc0 = (quad & 1) * 4;

    float acc[4][4];
    #pragma unroll
    for (int i = 0; i < 4; i++)
        #pragma unroll
        for (int j = 0; j < 4; j++) acc[i][j] = 0.f;

    for (int ciBase = 0; ciBase < CC; ciBase += 8) {
        for (int i = tid; i < 800; i += 128) {
            int ci = i / 100, rem = i % 100;
            int r = rem / 10, col = rem % 10;
            int gy = ty*8 + r - 1, gx = tx*8 + col - 1;
            float v = 0.f;
            if (gy >= 0 && gy < HH && gx >= 0 && gx < WWd)
                v = x[((size_t)(b*CC + ciBase + ci))*HWP + gy*WWd + gx];
            sIn[ci][r][col] = v;
        }
        for (int i = tid; i < 2304; i += 128) {
            int co = i & 31, t = (i >> 5) % 9, ci = i / 288;
            sW[ci][t][co] = w[((size_t)(coBase+co)*CC + ciBase + ci)*9 + t];
        }
        __syncthreads();
        #pragma unroll
        for (int ci = 0; ci < 8; ci++) {
            #pragma unroll
            for (int dy = 0; dy < 3; dy++) {
                #pragma unroll
                for (int dx = 0; dx < 3; dx++) {
                    float wv[4], iv[4];
                    #pragma unroll
                    for (int cc = 0; cc < 4; cc++) wv[cc] = sW[ci][dy*3+dx][grp*4+cc];
                    #pragma unroll
                    for (int pp = 0; pp < 4; pp++) iv[pp] = sIn[ci][pr+dy][pc0+dx+pp];
                    #pragma unroll
                    for (int cc = 0; cc < 4; cc++)
                        #pragma unroll
                        for (int pp = 0; pp < 4; pp++)
                            acc[cc][pp] += wv[cc] * iv[pp];
                }
            }
        }
        __syncthreads();
    }
    #pragma unroll
    for (int cc = 0; cc < 4; cc++) {
        int co = coBase + grp*4 + cc;
        size_t base = ((size_t)(b*CC + co))*HWP + (ty*8 + pr)*WWd + tx*8 + pc0;
        #pragma unroll
        for (int pp = 0; pp < 4; pp++) {
            if (ACCUM) out[base + pp] += acc[cc][pp];
            else       out[base + pp]  = acc[cc][pp];
        }
    }
}

// ---------------- direct 5x5 conv (Bayar, gated sel==1, accumulate) ---------
__global__ __launch_bounds__(128) void conv5_kernel(
    const float* __restrict__ x, const float* __restrict__ w, float* __restrict__ out)
{
    int b = blockIdx.z;
    if (g_sel[b] != 1) return;
    int tile = blockIdx.x;
    int ty = tile / 7, tx = tile % 7;
    int coBase = blockIdx.y * 32;

    __shared__ float sIn[8][12][12];
    __shared__ float sW[8][25][32];

    int tid = threadIdx.x;
    int quad = tid & 15, grp = tid >> 4;
    int pr = quad >> 1, pc0 = (quad & 1) * 4;

    float acc[4][4];
    #pragma unroll
    for (int i = 0; i < 4; i++)
        #pragma unroll
        for (int j = 0; j < 4; j++) acc[i][j] = 0.f;

    for (int ciBase = 0; ciBase < CC; ciBase += 8) {
        for (int i = tid; i < 1152; i += 128) {
            int ci = i / 144, rem = i % 144;
            int r = rem / 12, col = rem % 12;
            int gy = ty*8 + r - 2, gx = tx*8 + col - 2;
            float v = 0.f;
            if (gy >= 0 && gy < HH && gx >= 0 && gx < WWd)
                v = x[((size_t)(b*CC + ciBase + ci))*HWP + gy*WWd + gx];
            sIn[ci][r][col] = v;
        }
        for (int i = tid; i < 6400; i += 128) {
            int co = i & 31, t = (i >> 5) % 25, ci = i / 800;
            sW[ci][t][co] = w[((size_t)(coBase+co)*CC + ciBase + ci)*25 + t];
        }
        __syncthreads();
        #pragma unroll
        for (int ci = 0; ci < 8; ci++) {
            #pragma unroll
            for (int dy = 0; dy < 5; dy++) {
                #pragma unroll
                for (int dx = 0; dx < 5; dx++) {
                    float wv[4], iv[4];
                    #pragma unroll
                    for (int cc = 0; cc < 4; cc++) wv[cc] = sW[ci][dy*5+dx][grp*4+cc];
                    #pragma unroll
                    for (int pp = 0; pp < 4; pp++) iv[pp] = sIn[ci][pr+dy][pc0+dx+pp];
                    #pragma unroll
                    for (int cc = 0; cc < 4; cc++)
                        #pragma unroll
                        for (int pp = 0; pp < 4; pp++)
                            acc[cc][pp] += wv[cc] * iv[pp];
                }
            }
        }
        __syncthreads();
    }
    #pragma unroll
    for (int cc = 0; cc < 4; cc++) {
        int co = coBase + grp*4 + cc;
        size_t base = ((size_t)(b*CC + co))*HWP + (ty*8 + pr)*WWd + tx*8 + pc0;
        #pragma unroll
        for (int pp = 0; pp < 4; pp++) out[base + pp] += acc[cc][pp];
    }
}

// ---------------- depthwise convs (dense, all batches) -----------------------
__global__ __launch_bounds__(256) void dw_srm(const float* __restrict__ x,
                                              const float* __restrict__ kern)
{
    int b = blockIdx.z, ci = blockIdx.y;
    __shared__ float sIn[60][60];
    __shared__ float sK[75];
    int tid = threadIdx.x;
    for (int i = tid; i < 3600; i += 256) {
        int r = i / 60, c = i % 60;
        int gy = r - 2, gx = c - 2;
        float v = 0.f;
        if (gy >= 0 && gy < HH && gx >= 0 && gx < WWd)
            v = x[((size_t)(b*CC + ci))*HWP + gy*WWd + gx];
        sIn[r][c] = v;
    }
    if (tid < 75) sK[tid] = kern[(size_t)ci*75 + tid];
    __syncthreads();
    for (int p = tid; p < HWP; p += 256) {
        int pr = p / WWd, pc = p % WWd;
        float s0 = 0.f, s1 = 0.f, s2 = 0.f;
        #pragma unroll
        for (int dy = 0; dy < 5; dy++) {
            #pragma unroll
            for (int dx = 0; dx < 5; dx++) {
                float v = sIn[pr+dy][pc+dx];
                int t = dy*5 + dx;
                s0 += v * sK[t];
                s1 += v * sK[25 + t];
                s2 += v * sK[50 + t];
            }
        }
        s0 = fminf(fmaxf(s0, -3.f), 3.f);
        s1 = fminf(fmaxf(s1, -3.f), 3.f);
        s2 = fminf(fmaxf(s2, -3.f), 3.f);
        size_t base = ((size_t)b*3*CC + 3*ci) * HWP + p;
        g_y2[base]           = s0;
        g_y2[base + HWP]     = s1;
        g_y2[base + 2*HWP]   = s2;
    }
}

__global__ __launch_bounds__(256) void dw_hf(const float* __restrict__ x,
                                             const float* __restrict__ kern)
{
    int b = blockIdx.z, ci = blockIdx.y;
    __shared__ float sIn[58][58];
    __shared__ float sK[9];
    int tid = threadIdx.x;
    for (int i = tid; i < 3364; i += 256) {
        int r = i / 58, c = i % 58;
        int gy = r - 1, gx = c - 1;
        float v = 0.f;
        if (gy >= 0 && gy < HH && gx >= 0 && gx < WWd)
            v = x[((size_t)(b*CC + ci))*HWP + gy*WWd + gx];
        sIn[r][c] = v;
    }
    if (tid < 9) sK[tid] = kern[(size_t)ci*9 + tid];
    __syncthreads();
    for (int p = tid; p < HWP; p += 256) {
        int pr = p / WWd, pc = p % WWd;
        float s = 0.f;
        #pragma unroll
        for (int dy = 0; dy < 3; dy++)
            #pragma unroll
            for (int dx = 0; dx < 3; dx++)
                s += sIn[pr+dy][pc+dx] * sK[dy*3+dx];
        g_y3[((size_t)(b*CC + ci))*HWP + p] = s;
    }
}

// ---------------- 1x1 conv = per-batch GEMM: Z[co][p] = sum_k W[co][k]*Y[k][p]
__global__ __launch_bounds__(256) void gemm1x1(const float* __restrict__ Wm,
                                               const float* __restrict__ Y,
                                               float* __restrict__ Z, int K)
{
    int b = blockIdx.z;
    const float* Yb = Y + (size_t)b * K * HWP;
    float* Zb = Z + (size_t)b * CC * HWP;
    int p0 = blockIdx.x * 64, co0 = blockIdx.y * 64;

    __shared__ float sW[16][65];
    __shared__ float sY[16][65];

    int tid = threadIdx.x;
    int pcol = tid & 15, crow = tid >> 4;
    float acc[4][4];
    #pragma unroll
    for (int i = 0; i < 4; i++)
        #pragma unroll
        for (int j = 0; j < 4; j++) acc[i][j] = 0.f;

    for (int kb = 0; kb < K; kb += 16) {
        for (int i = tid; i < 1024; i += 256) {
            int kk = i & 15, j = i >> 4;
            sW[kk][j] = Wm[(size_t)(co0 + j)*K + kb + kk];
        }
        for (int i = tid; i < 1024; i += 256) {
            int kk = i >> 6, j = i & 63;
            sY[kk][j] = Yb[(size_t)(kb + kk)*HWP + p0 + j];
        }
        __syncthreads();
        #pragma unroll
        for (int kk = 0; kk < 16; kk++) {
            float wv[4], yv[4];
            #pragma unroll
            for (int cc = 0; cc < 4; cc++) wv[cc] = sW[kk][crow*4 + cc];
            #pragma unroll
            for (int pp = 0; pp < 4; pp++) yv[pp] = sY[kk][pcol*4 + pp];
            #pragma unroll
            for (int cc = 0; cc < 4; cc++)
                #pragma unroll
                for (int pp = 0; pp < 4; pp++)
                    acc[cc][pp] += wv[cc] * yv[pp];
        }
        __syncthreads();
    }
    #pragma unroll
    for (int cc = 0; cc < 4; cc++) {
        size_t base = (size_t)(co0 + crow*4 + cc)*HWP + p0 + pcol*4;
        #pragma unroll
        for (int pp = 0; pp < 4; pp++) Zb[base + pp] = acc[cc][pp];
    }
}

// ---------------- BN stats + apply -------------------------------------------
__global__ void zero_stats() {
    int i = threadIdx.x;
    if (i < CC) { g_sum2[i] = 0.f; g_sq2[i] = 0.f; g_sum3[i] = 0.f; g_sq3[i] = 0.f; }
}

__global__ __launch_bounds__(256) void bn_reduce(const float* __restrict__ Z, int which) {
    int b = blockIdx.x, c = blockIdx.y;
    const float* p = Z + ((size_t)b*CC + c)*HWP;
    float s = 0.f, q = 0.f;
    for (int i = threadIdx.x; i < HWP; i += 256) {
        float v = p[i]; s += v; q += v*v;
    }
    __shared__ float ss[256], sq[256];
    ss[threadIdx.x] = s; sq[threadIdx.x] = q; __syncthreads();
    for (int o = 128; o > 0; o >>= 1) {
        if (threadIdx.x < o) { ss[threadIdx.x] += ss[threadIdx.x+o]; sq[threadIdx.x] += sq[threadIdx.x+o]; }
        __syncthreads();
    }
    if (threadIdx.x == 0) {
        if (which == 0) { atomicAdd(&g_sum2[c], ss[0]); atomicAdd(&g_sq2[c], sq[0]); }
        else            { atomicAdd(&g_sum3[c], ss[0]); atomicAdd(&g_sq3[c], sq[0]); }
    }
}

__global__ void bn_final() {
    int c = threadIdx.x;
    if (c >= CC) return;
    const float inv = 1.0f / (float)(BB * HWP);
    float m2 = g_sum2[c] * inv;
    float v2 = g_sq2[c] * inv - m2*m2;
    g_mrs2[c] = m2; g_mrs2[CC + c] = rsqrtf(v2 + BN_EPS);
    float m3 = g_sum3[c] * inv;
    float v3 = g_sq3[c] * inv - m3*m3;
    g_mrs3[c] = m3; g_mrs3[CC + c] = rsqrtf(v3 + BN_EPS);
}

__global__ __launch_bounds__(256) void bn_apply(
    const float* __restrict__ sg, const float* __restrict__ sb,
    const float* __restrict__ hg, const float* __restrict__ hb,
    float* __restrict__ out)
{
    int b = blockIdx.z;
    int sel = g_sel[b];
    if (sel < 2) return;
    int c = blockIdx.y;
    int p = blockIdx.x * 256 + threadIdx.x;
    if (p >= HWP) return;
    const float* Z   = (sel == 2) ? g_z2   : g_z3;
    const float* mrs = (sel == 2) ? g_mrs2 : g_mrs3;
    float gamma = (sel == 2) ? sg[c] : hg[c];
    float beta  = (sel == 2) ? sb[c] : hb[c];
    float v = Z[((size_t)b*CC + c)*HWP + p];
    float y = (v - mrs[c]) * mrs[CC + c] * gamma + beta;
    out[((size_t)b*CC + c)*HWP + p] += fmaxf(y, 0.f);
}

// ---------------- launch ------------------------------------------------------
extern "C" void kernel_launch(void* const* d_in, const int* in_sizes, int n_in,
                              void* d_out, int out_size)
{
    const float* x        = (const float*)d_in[0];
    const float* Wg       = (const float*)d_in[1];
    const float* cd_w     = (const float*)d_in[2];
    const float* bayar_w  = (const float*)d_in[3];
    const float* srm_k    = (const float*)d_in[4];
    const float* srm_ow   = (const float*)d_in[5];
    const float* srm_g    = (const float*)d_in[6];
    const float* srm_b    = (const float*)d_in[7];
    const float* hf_k     = (const float*)d_in[8];
    const float* hf_ow    = (const float*)d_in[9];
    const float* hf_g     = (const float*)d_in[10];
    const float* hf_b     = (const float*)d_in[11];
    const float* shared_w = (const float*)d_in[12];
    float* out = (float*)d_out;

    void *p_weff, *p_k5, *p_y2, *p_z2, *p_y3, *p_z3;
    cudaGetSymbolAddress(&p_weff, g_weff);
    cudaGetSymbolAddress(&p_k5,   g_k5);
    cudaGetSymbolAddress(&p_y2,   g_y2);
    cudaGetSymbolAddress(&p_z2,   g_z2);
    cudaGetSymbolAddress(&p_y3,   g_y3);
    cudaGetSymbolAddress(&p_z3,   g_z3);

    // gating
    pool_kernel<<<BB*CC, 256>>>(x);
    gating_kernel<<<1, 32>>>(Wg, out + (size_t)BB*CC*HWP);

    // weight prep
    prep_cd<<<(CC*CC + 255)/256, 256>>>(cd_w);
    prep_bayar<<<(CC*CC + 255)/256, 256>>>(bayar_w);

    // shared conv (dense, writes out base)
    conv3_kernel<-1, false><<<dim3(49, 4, BB), 128>>>(x, shared_w, out);

    // SRM expert pipeline (dense through BN stats)
    dw_srm<<<dim3(1, CC, BB), 256>>>(x, srm_k);
    gemm1x1<<<dim3(49, 2, BB), 256>>>(srm_ow, (const float*)p_y2, (float*)p_z2, 3*CC);

    // HF expert pipeline
    dw_hf<<<dim3(1, CC, BB), 256>>>(x, hf_k);
    gemm1x1<<<dim3(49, 2, BB), 256>>>(hf_ow, (const float*)p_y3, (float*)p_z3, CC);

    // BN stats
    zero_stats<<<1, 128>>>();
    bn_reduce<<<dim3(BB, CC), 256>>>((const float*)p_z2, 0);
    bn_reduce<<<dim3(BB, CC), 256>>>((const float*)p_z3, 1);
    bn_final<<<1, CC>>>();

    // gated expert contributions (accumulate into out)
    conv3_kernel<0, true><<<dim3(49, 4, BB), 128>>>(x, (const float*)p_weff, out);
    conv5_kernel<<<dim3(49, 4, BB), 128>>>(x, (const float*)p_k5, out);
    bn_apply<<<dim3(13, CC, BB), 256>>>(srm_g, srm_b, hf_g, hf_b, out);
}

// round 2
// speedup vs baseline: 1.2393x; 1.2393x over previous
#include <cuda_runtime.h>
#include <cstdint>

#define BB  32
#define CC  128
#define HH  56
#define WWd 56
#define HWP 3136
#define EE  4
#define THETA 0.7f
#define BN_EPS 1e-5f

// ---------------- scratch (device globals) ----------------------------------
__device__ float g_pool[BB*CC];
__device__ int   g_sel[BB];
__device__ float g_w3[2*CC*CC*9];            // slot0: shared ; slot1: shared + cd_eff
__device__ float g_k5[CC*CC*25];             // bayar + padded shared
__device__ float g_y2[(size_t)BB*3*CC*HWP];  // SRM depthwise out (clipped)
__device__ float g_z2[(size_t)BB*CC*HWP];    // SRM 1x1 out (pre-BN, selected batches only)
__device__ float g_y3[(size_t)BB*CC*HWP];    // HF depthwise out
__device__ float g_z3[(size_t)BB*CC*HWP];    // HF 1x1 out
__device__ float g_sum2[CC], g_sq2[CC], g_sum3[CC], g_sq3[CC];
__device__ float g_mrs2[2*CC], g_mrs3[2*CC];

// ---------------- gating -----------------------------------------------------
__global__ void pool_kernel(const float* __restrict__ x) {
    int bc = blockIdx.x;
    const float* p = x + (size_t)bc * HWP;
    float s = 0.f;
    for (int i = threadIdx.x; i < HWP; i += 256) s += p[i];
    __shared__ float sm[256];
    sm[threadIdx.x] = s; __syncthreads();
    for (int o = 128; o > 0; o >>= 1) {
        if (threadIdx.x < o) sm[threadIdx.x] += sm[threadIdx.x + o];
        __syncthreads();
    }
    if (threadIdx.x == 0) g_pool[bc] = sm[0] * (1.0f / (float)HWP);
}

__global__ void gating_kernel(const float* __restrict__ Wg, float* __restrict__ tail) {
    int b = threadIdx.x;
    __shared__ float cnt[EE];
    if (b < EE) cnt[b] = 0.f;
    __syncthreads();
    if (b < BB) {
        float logit[EE];
        for (int e = 0; e < EE; e++) {
            float s = 0.f;
            for (int c = 0; c < CC; c++) s += g_pool[b*CC + c] * Wg[c*EE + e];
            logit[e] = s;
        }
        int best = 0; float bv = logit[0];
        for (int e = 1; e < EE; e++) if (logit[e] > bv) { bv = logit[e]; best = e; }
        g_sel[b] = best;
        for (int e = 0; e < EE; e++) tail[9 + b*EE + e] = (e == best) ? 1.0f : 0.0f;
        atomicAdd(&cnt[best], 1.0f);
    }
    __syncthreads();
    if (b == 0) {
        float mean = 0.f;
        for (int e = 0; e < EE; e++) mean += cnt[e];
        mean *= (1.0f / EE);
        float var = 0.f;
        for (int e = 0; e < EE; e++) { float d = cnt[e] - mean; var += d*d; }
        var *= (1.0f / EE);
        tail[0] = var / (mean*mean + 1e-10f);
        for (int e = 0; e < EE; e++) {
            tail[1 + e] = cnt[e];
            tail[5 + e] = cnt[e];
        }
    }
}

// ---------------- weight prep -------------------------------------------------
__global__ void prep_w3(const float* __restrict__ shared_w, const float* __restrict__ cd_w) {
    int oi = blockIdx.x * blockDim.x + threadIdx.x;
    if (oi >= CC*CC) return;
    const float* sh = shared_w + (size_t)oi * 9;
    const float* cd = cd_w + (size_t)oi * 9;
    float s = 0.f;
    #pragma unroll
    for (int t = 0; t < 9; t++) s += cd[t];
    #pragma unroll
    for (int t = 0; t < 9; t++) {
        float shv = sh[t];
        g_w3[(size_t)oi*9 + t] = shv;                                            // slot 0
        g_w3[(size_t)(CC*CC + oi)*9 + t] = shv + cd[t] - ((t == 4) ? THETA*s : 0.f); // slot 1
    }
}

__global__ void prep_k5(const float* __restrict__ raw, const float* __restrict__ shared_w) {
    int oi = blockIdx.x * blockDim.x + threadIdx.x;
    if (oi >= CC*CC) return;
    const float* r = raw + (size_t)oi * 24;
    const float* sh = shared_w + (size_t)oi * 9;
    float s = 0.f;
    #pragma unroll
    for (int t = 0; t < 24; t++) s += r[t];
    float inv = 1.0f / s;
    float k[25];
    #pragma unroll
    for (int t = 0; t < 12; t++) k[t] = r[t] * inv;
    k[12] = -1.0f;
    #pragma unroll
    for (int t = 12; t < 24; t++) k[t+1] = r[t] * inv;
    // embed shared 3x3 at center (pad 2 conv == pad 1 conv of embedded kernel)
    #pragma unroll
    for (int dy = 0; dy < 3; dy++)
        #pragma unroll
        for (int dx = 0; dx < 3; dx++)
            k[(dy+1)*5 + (dx+1)] += sh[dy*3+dx];
    float* o = g_k5 + (size_t)oi * 25;
    #pragma unroll
    for (int t = 0; t < 25; t++) o[t] = k[t];
}

// ---------------- direct 3x3 conv (handles sel!=1 batches, writes out) --------
// block: 32 out-channels x 8x8 pixels, 128 threads, each thread 4co x 4px
__global__ __launch_bounds__(128) void conv3_kernel(
    const float* __restrict__ x, float* __restrict__ out)
{
    int b = blockIdx.z;
    int sel = g_sel[b];
    if (sel == 1) return;                       // Bayar batches handled by conv5
    const float* w = g_w3 + (size_t)((sel == 0) ? CC*CC*9 : 0);
    int tile = blockIdx.x;
    int ty = tile / 7, tx = tile % 7;
    int coBase = blockIdx.y * 32;

    __shared__ float sIn[8][10][12];            // padded rows for float4 loads
    __shared__ float sW[8][9][32];

    int tid = threadIdx.x;
    int quad = tid & 15, grp = tid >> 4;
    int pr = quad >> 1, pc0 = (quad & 1) * 4;

    float acc[4][4];
    #pragma unroll
    for (int i = 0; i < 4; i++)
        #pragma unroll
        for (int j = 0; j < 4; j++) acc[i][j] = 0.f;

    for (int ciBase = 0; ciBase < CC; ciBase += 8) {
        for (int i = tid; i < 800; i += 128) {
            int ci = i / 100, rem = i % 100;
            int r = rem / 10, col = rem % 10;
            int gy = ty*8 + r - 1, gx = tx*8 + col - 1;
            float v = 0.f;
            if (gy >= 0 && gy < HH && gx >= 0 && gx < WWd)
                v = x[((size_t)(b*CC + ciBase + ci))*HWP + gy*WWd + gx];
            sIn[ci][r][col] = v;
        }
        for (int i = tid; i < 2304; i += 128) {
            int co = i & 31, t = (i >> 5) % 9, ci = i / 288;
            sW[ci][t][co] = w[((size_t)(coBase+co)*CC + ciBase + ci)*9 + t];
        }
        __syncthreads();
        #pragma unroll
        for (int ci = 0; ci < 8; ci++) {
            #pragma unroll
            for (int dy = 0; dy < 3; dy++) {
                float4 i0 = *(const float4*)&sIn[ci][pr+dy][pc0];
                float4 i1 = *(const float4*)&sIn[ci][pr+dy][pc0+4];
                float r8[8] = {i0.x,i0.y,i0.z,i0.w,i1.x,i1.y,i1.z,i1.w};
                #pragma unroll
                for (int dx = 0; dx < 3; dx++) {
                    float4 wv = *(const float4*)&sW[ci][dy*3+dx][grp*4];
                    float wr[4] = {wv.x, wv.y, wv.z, wv.w};
                    #pragma unroll
                    for (int cc = 0; cc < 4; cc++)
                        #pragma unroll
                        for (int pp = 0; pp < 4; pp++)
                            acc[cc][pp] += wr[cc] * r8[dx+pp];
                }
            }
        }
        __syncthreads();
    }
    #pragma unroll
    for (int cc = 0; cc < 4; cc++) {
        int co = coBase + grp*4 + cc;
        size_t base = ((size_t)(b*CC + co))*HWP + (ty*8 + pr)*WWd + tx*8 + pc0;
        #pragma unroll
        for (int pp = 0; pp < 4; pp++) out[base + pp] = acc[cc][pp];
    }
}

// ---------------- direct 5x5 conv (sel==1 batches, writes out) ----------------
__global__ __launch_bounds__(128) void conv5_kernel(
    const float* __restrict__ x, float* __restrict__ out)
{
    int b = blockIdx.z;
    if (g_sel[b] != 1) return;
    int tile = blockIdx.x;
    int ty = tile / 7, tx = tile % 7;
    int coBase = blockIdx.y * 32;

    __shared__ float sIn[8][12][16];            // padded for float4
    __shared__ float sW[8][25][32];

    int tid = threadIdx.x;
    int quad = tid & 15, grp = tid >> 4;
    int pr = quad >> 1, pc0 = (quad & 1) * 4;

    float acc[4][4];
    #pragma unroll
    for (int i = 0; i < 4; i++)
        #pragma unroll
        for (int j = 0; j < 4; j++) acc[i][j] = 0.f;

    for (int ciBase = 0; ciBase < CC; ciBase += 8) {
        for (int i = tid; i < 1152; i += 128) {
            int ci = i / 144, rem = i % 144;
            int r = rem / 12, col = rem % 12;
            int gy = ty*8 + r - 2, gx = tx*8 + col - 2;
            float v = 0.f;
            if (gy >= 0 && gy < HH && gx >= 0 && gx < WWd)
                v = x[((size_t)(b*CC + ciBase + ci))*HWP + gy*WWd + gx];
            sIn[ci][r][col] = v;
        }
        for (int i = tid; i < 6400; i += 128) {
            int co = i & 31, t = (i >> 5) % 25, ci = i / 800;
            sW[ci][t][co] = g_k5[((size_t)(coBase+co)*CC + ciBase + ci)*25 + t];
        }
        __syncthreads();
        #pragma unroll
        for (int ci = 0; ci < 8; ci++) {
            #pragma unroll
            for (int dy = 0; dy < 5; dy++) {
                float4 i0 = *(const float4*)&sIn[ci][pr+dy][pc0];
                float4 i1 = *(const float4*)&sIn[ci][pr+dy][pc0+4];
                float4 i2 = *(const float4*)&sIn[ci][pr+dy][pc0+8];
                float r12[12] = {i0.x,i0.y,i0.z,i0.w,i1.x,i1.y,i1.z,i1.w,i2.x,i2.y,i2.z,i2.w};
                #pragma unroll
                for (int dx = 0; dx < 5; dx++) {
                    float4 wv = *(const float4*)&sW[ci][dy*5+dx][grp*4];
                    float wr[4] = {wv.x, wv.y, wv.z, wv.w};
                    #pragma unroll
                    for (int cc = 0; cc < 4; cc++)
                        #pragma unroll
                        for (int pp = 0; pp < 4; pp++)
                            acc[cc][pp] += wr[cc] * r12[dx+pp];
                }
            }
        }
        __syncthreads();
    }
    #pragma unroll
    for (int cc = 0; cc < 4; cc++) {
        int co = coBase + grp*4 + cc;
        size_t base = ((size_t)(b*CC + co))*HWP + (ty*8 + pr)*WWd + tx*8 + pc0;
        #pragma unroll
        for (int pp = 0; pp < 4; pp++) out[base + pp] = acc[cc][pp];
    }
}

// ---------------- depthwise convs (dense, all batches) ------------------------
__global__ __launch_bounds__(256) void dw_srm(const float* __restrict__ x,
                                              const float* __restrict__ kern)
{
    int b = blockIdx.z, ci = blockIdx.y;
    __shared__ float sIn[60][60];
    __shared__ float sK[75];
    int tid = threadIdx.x;
    for (int i = tid; i < 3600; i += 256) {
        int r = i / 60, c = i % 60;
        int gy = r - 2, gx = c - 2;
        float v = 0.f;
        if (gy >= 0 && gy < HH && gx >= 0 && gx < WWd)
            v = x[((size_t)(b*CC + ci))*HWP + gy*WWd + gx];
        sIn[r][c] = v;
    }
    if (tid < 75) sK[tid] = kern[(size_t)ci*75 + tid];
    __syncthreads();
    for (int p = tid; p < HWP; p += 256) {
        int pr = p / WWd, pc = p % WWd;
        float s0 = 0.f, s1 = 0.f, s2 = 0.f;
        #pragma unroll
        for (int dy = 0; dy < 5; dy++) {
            #pragma unroll
            for (int dx = 0; dx < 5; dx++) {
                float v = sIn[pr+dy][pc+dx];
                int t = dy*5 + dx;
                s0 += v * sK[t];
                s1 += v * sK[25 + t];
                s2 += v * sK[50 + t];
            }
        }
        s0 = fminf(fmaxf(s0, -3.f), 3.f);
        s1 = fminf(fmaxf(s1, -3.f), 3.f);
        s2 = fminf(fmaxf(s2, -3.f), 3.f);
        size_t base = ((size_t)b*3*CC + 3*ci) * HWP + p;
        g_y2[base]           = s0;
        g_y2[base + HWP]     = s1;
        g_y2[base + 2*HWP]   = s2;
    }
}

__global__ __launch_bounds__(256) void dw_hf(const float* __restrict__ x,
                                             const float* __restrict__ kern)
{
    int b = blockIdx.z, ci = blockIdx.y;
    __shared__ float sIn[58][58];
    __shared__ float sK[9];
    int tid = threadIdx.x;
    for (int i = tid; i < 3364; i += 256) {
        int r = i / 58, c = i % 58;
        int gy = r - 1, gx = c - 1;
        float v = 0.f;
        if (gy >= 0 && gy < HH && gx >= 0 && gx < WWd)
            v = x[((size_t)(b*CC + ci))*HWP + gy*WWd + gx];
        sIn[r][c] = v;
    }
    if (tid < 9) sK[tid] = kern[(size_t)ci*9 + tid];
    __syncthreads();
    for (int p = tid; p < HWP; p += 256) {
        int pr = p / WWd, pc = p % WWd;
        float s = 0.f;
        #pragma unroll
        for (int dy = 0; dy < 3; dy++)
            #pragma unroll
            for (int dx = 0; dx < 3; dx++)
                s += sIn[pr+dy][pc+dx] * sK[dy*3+dx];
        g_y3[((size_t)(b*CC + ci))*HWP + p] = s;
    }
}

// ---------------- 1x1 conv GEMM + fused BN stats -------------------------------
// Z[co][p] = sum_k W[co][k]*Y[k][p] ; atomically accumulates per-channel sum/sumsq
__global__ __launch_bounds__(256) void gemm1x1(const float* __restrict__ Wm,
                                               const float* __restrict__ Y,
                                               float* __restrict__ Z, int K,
                                               int expert_id,
                                               float* __restrict__ gsum,
                                               float* __restrict__ gsq)
{
    int b = blockIdx.z;
    bool store = (g_sel[b] == expert_id);
    const float* Yb = Y + (size_t)b * K * HWP;
    float* Zb = Z + (size_t)b * CC * HWP;
    int p0 = blockIdx.x * 64, co0 = blockIdx.y * 64;

    __shared__ float sW[16][65];
    __shared__ float sY[16][65];

    int tid = threadIdx.x;
    int pcol = tid & 15, crow = tid >> 4;
    float acc[4][4];
    #pragma unroll
    for (int i = 0; i < 4; i++)
        #pragma unroll
        for (int j = 0; j < 4; j++) acc[i][j] = 0.f;

    for (int kb = 0; kb < K; kb += 16) {
        for (int i = tid; i < 1024; i += 256) {
            int kk = i & 15, j = i >> 4;
            sW[kk][j] = Wm[(size_t)(co0 + j)*K + kb + kk];
        }
        for (int i = tid; i < 1024; i += 256) {
            int kk = i >> 6, j = i & 63;
            sY[kk][j] = Yb[(size_t)(kb + kk)*HWP + p0 + j];
        }
        __syncthreads();
        #pragma unroll
        for (int kk = 0; kk < 16; kk++) {
            float wv[4], yv[4];
            #pragma unroll
            for (int cc = 0; cc < 4; cc++) wv[cc] = sW[kk][crow*4 + cc];
            #pragma unroll
            for (int pp = 0; pp < 4; pp++) yv[pp] = sY[kk][pcol*4 + pp];
            #pragma unroll
            for (int cc = 0; cc < 4; cc++)
                #pragma unroll
                for (int pp = 0; pp < 4; pp++)
                    acc[cc][pp] += wv[cc] * yv[pp];
        }
        __syncthreads();
    }

    // store + fused BN stats
    #pragma unroll
    for (int cc = 0; cc < 4; cc++) {
        int co = co0 + crow*4 + cc;
        if (store) {
            size_t base = (size_t)co*HWP + p0 + pcol*4;
            #pragma unroll
            for (int pp = 0; pp < 4; pp++) Zb[base + pp] = acc[cc][pp];
        }
        float s = 0.f, q = 0.f;
        #pragma unroll
        for (int pp = 0; pp < 4; pp++) { s += acc[cc][pp]; q += acc[cc][pp]*acc[cc][pp]; }
        #pragma unroll
        for (int o = 8; o > 0; o >>= 1) {
            s += __shfl_down_sync(0xffffffffu, s, o, 16);
            q += __shfl_down_sync(0xffffffffu, q, o, 16);
        }
        if (pcol == 0) {
            atomicAdd(&gsum[co], s);
            atomicAdd(&gsq[co], q);
        }
    }
}

// ---------------- BN finalize + apply ------------------------------------------
__global__ void zero_stats() {
    int i = threadIdx.x;
    if (i < CC) { g_sum2[i] = 0.f; g_sq2[i] = 0.f; g_sum3[i] = 0.f; g_sq3[i] = 0.f; }
}

__global__ void bn_final() {
    int c = threadIdx.x;
    if (c >= CC) return;
    const float inv = 1.0f / (float)(BB * HWP);
    float m2 = g_sum2[c] * inv;
    float v2 = g_sq2[c] * inv - m2*m2;
    g_mrs2[c] = m2; g_mrs2[CC + c] = rsqrtf(v2 + BN_EPS);
    float m3 = g_sum3[c] * inv;
    float v3 = g_sq3[c] * inv - m3*m3;
    g_mrs3[c] = m3; g_mrs3[CC + c] = rsqrtf(v3 + BN_EPS);
}

__global__ __launch_bounds__(256) void bn_apply(
    const float* __restrict__ sg, const float* __restrict__ sb,
    const float* __restrict__ hg, const float* __restrict__ hb,
    float* __restrict__ out)
{
    int b = blockIdx.z;
    int sel = g_sel[b];
    if (sel < 2) return;
    int c = blockIdx.y;
    int p = blockIdx.x * 256 + threadIdx.x;
    if (p >= HWP) return;
    const float* Z   = (sel == 2) ? g_z2   : g_z3;
    const float* mrs = (sel == 2) ? g_mrs2 : g_mrs3;
    float gamma = (sel == 2) ? sg[c] : hg[c];
    float beta  = (sel == 2) ? sb[c] : hb[c];
    float v = Z[((size_t)b*CC + c)*HWP + p];
    float y = (v - mrs[c]) * mrs[CC + c] * gamma + beta;
    out[((size_t)b*CC + c)*HWP + p] += fmaxf(y, 0.f);
}

// ---------------- launch --------------------------------------------------------
extern "C" void kernel_launch(void* const* d_in, const int* in_sizes, int n_in,
                              void* d_out, int out_size)
{
    const float* x        = (const float*)d_in[0];
    const float* Wg       = (const float*)d_in[1];
    const float* cd_w     = (const float*)d_in[2];
    const float* bayar_w  = (const float*)d_in[3];
    const float* srm_k    = (const float*)d_in[4];
    const float* srm_ow   = (const float*)d_in[5];
    const float* srm_g    = (const float*)d_in[6];
    const float* srm_b    = (const float*)d_in[7];
    const float* hf_k     = (const float*)d_in[8];
    const float* hf_ow    = (const float*)d_in[9];
    const float* hf_g     = (const float*)d_in[10];
    const float* hf_b     = (const float*)d_in[11];
    const float* shared_w = (const float*)d_in[12];
    float* out = (float*)d_out;

    void *p_y2, *p_z2, *p_y3, *p_z3, *p_s2, *p_q2, *p_s3, *p_q3;
    cudaGetSymbolAddress(&p_y2, g_y2);
    cudaGetSymbolAddress(&p_z2, g_z2);
    cudaGetSymbolAddress(&p_y3, g_y3);
    cudaGetSymbolAddress(&p_z3, g_z3);
    cudaGetSymbolAddress(&p_s2, g_sum2);
    cudaGetSymbolAddress(&p_q2, g_sq2);
    cudaGetSymbolAddress(&p_s3, g_sum3);
    cudaGetSymbolAddress(&p_q3, g_sq3);

    // gating (g_sel needed by convs/gemms)
    pool_kernel<<<BB*CC, 256>>>(x);
    gating_kernel<<<1, 32>>>(Wg, out + (size_t)BB*CC*HWP);

    // weight prep
    prep_w3<<<(CC*CC + 255)/256, 256>>>(shared_w, cd_w);
    prep_k5<<<(CC*CC + 255)/256, 256>>>(bayar_w, shared_w);
    zero_stats<<<1, 128>>>();

    // SRM / HF expert pipelines (dense through BN stats, fused into gemm)
    dw_srm<<<dim3(1, CC, BB), 256>>>(x, srm_k);
    gemm1x1<<<dim3(49, 2, BB), 256>>>(srm_ow, (const float*)p_y2, (float*)p_z2, 3*CC,
                                      2, (float*)p_s2, (float*)p_q2);
    dw_hf<<<dim3(1, CC, BB), 256>>>(x, hf_k);
    gemm1x1<<<dim3(49, 2, BB), 256>>>(hf_ow, (const float*)p_y3, (float*)p_z3, CC,
                                      3, (float*)p_s3, (float*)p_q3);
    bn_final<<<1, CC>>>();

    // fused shared+expert convs (each batch written exactly once)
    conv3_kernel<<<dim3(49, 4, BB), 128>>>(x, out);
    conv5_kernel<<<dim3(49, 4, BB), 128>>>(x, out);

    // SRM/HF batches: add BN-ReLU'd expert output
    bn_apply<<<dim3(13, CC, BB), 256>>>(srm_g, srm_b, hf_g, hf_b, out);
}